// round 1
// baseline (speedup 1.0000x reference)
#include <cuda_runtime.h>

// MKMMD loss: source (256,512) f32, target (256,512) f32 -> scalar f32.
// total = concat -> N=512 rows, D=512.
// result = (10*N + 2*sum_{i<j} s_i s_j (kL2+kL1)) / B^2, s = +/-1 by half.
// bw_x = (2*S_upper_x)/(N^2-N)/100 ; k = sum_{m=0..4} exp(-d/(bw*10^m))

#define NROWS 512
#define BHALF 256
#define DDIM  512
#define TILE  64
#define NSPLIT 4
#define SW    65   // odd pad -> conflict-free LDS in compute loop

__device__ float g_slabL1[NSPLIT][NROWS * NROWS];
__device__ float g_slabL2[NSPLIT][NROWS * NROWS];
__device__ float g_sumL1;
__device__ float g_sumL2;

__global__ void init_kernel(float* out) {
    g_sumL1 = 0.0f;
    g_sumL2 = 0.0f;
    // diagonal contribution: 512 rows * (5+5) * s_i^2 / B^2
    out[0] = 5120.0f / 65536.0f;
}

__global__ __launch_bounds__(256) void dist_kernel(
    const float* __restrict__ src, const float* __restrict__ tgt)
{
    __shared__ float As[TILE][SW];
    __shared__ float Bs[TILE][SW];

    const int tid = threadIdx.x;
    const int tx = tid & 15;
    const int ty = tid >> 4;

    // decode upper-triangle tile index (36 tiles over 8x8 tile grid)
    int t = blockIdx.x;
    int ti = 0;
    while (t >= 8 - ti) { t -= 8 - ti; ti++; }
    const int tj = ti + t;
    const int s = blockIdx.y;

    const int i0 = ti * TILE;
    const int j0 = tj * TILE;
    const float* Ap = (i0 < BHALF) ? (src + i0 * DDIM) : (tgt + (i0 - BHALF) * DDIM);
    const float* Bp = (j0 < BHALF) ? (src + j0 * DDIM) : (tgt + (j0 - BHALF) * DDIM);
    const int k00 = s * (DDIM / NSPLIT);   // 128-wide split, two 64-chunks

    float l1a[4][4], l2a[4][4];
#pragma unroll
    for (int u = 0; u < 4; u++)
#pragma unroll
        for (int v = 0; v < 4; v++) { l1a[u][v] = 0.0f; l2a[u][v] = 0.0f; }

    for (int c = 0; c < 2; ++c) {
        const int kb = k00 + c * 64;
        // load 64 rows x 64 cols of each tile, coalesced, conflict-free STS
#pragma unroll
        for (int q = 0; q < 16; ++q) {
            int e = (q << 8) + tid;      // 0..4095
            int r = e >> 6;
            int k = e & 63;
            As[r][k] = Ap[r * DDIM + kb + k];
            Bs[r][k] = Bp[r * DDIM + kb + k];
        }
        __syncthreads();

#pragma unroll 4
        for (int k = 0; k < 64; ++k) {
            float a0 = As[ty][k];
            float a1 = As[ty + 16][k];
            float a2 = As[ty + 32][k];
            float a3 = As[ty + 48][k];
            float b0 = Bs[tx][k];
            float b1 = Bs[tx + 16][k];
            float b2 = Bs[tx + 32][k];
            float b3 = Bs[tx + 48][k];
            float av[4] = {a0, a1, a2, a3};
            float bv[4] = {b0, b1, b2, b3};
#pragma unroll
            for (int u = 0; u < 4; u++)
#pragma unroll
                for (int v = 0; v < 4; v++) {
                    float d = av[u] - bv[v];
                    l1a[u][v] += fabsf(d);
                    l2a[u][v] = fmaf(d, d, l2a[u][v]);
                }
        }
        __syncthreads();
    }

    // write slabs + masked upper-triangle partial sums for bandwidth
    float s1 = 0.0f, s2 = 0.0f;
#pragma unroll
    for (int u = 0; u < 4; u++) {
        const int i = i0 + ty + 16 * u;
#pragma unroll
        for (int v = 0; v < 4; v++) {
            const int j = j0 + tx + 16 * v;
            const int idx = i * NROWS + j;
            g_slabL1[s][idx] = l1a[u][v];
            g_slabL2[s][idx] = l2a[u][v];
            if (ti < tj || j > i) { s1 += l1a[u][v]; s2 += l2a[u][v]; }
        }
    }

    // block reduce -> atomicAdd
#pragma unroll
    for (int o = 16; o > 0; o >>= 1) {
        s1 += __shfl_down_sync(0xffffffffu, s1, o);
        s2 += __shfl_down_sync(0xffffffffu, s2, o);
    }
    __shared__ float rs1[8], rs2[8];
    if ((tid & 31) == 0) { rs1[tid >> 5] = s1; rs2[tid >> 5] = s2; }
    __syncthreads();
    if (tid == 0) {
        float a = 0.0f, b = 0.0f;
#pragma unroll
        for (int w = 0; w < 8; ++w) { a += rs1[w]; b += rs2[w]; }
        atomicAdd(&g_sumL1, a);
        atomicAdd(&g_sumL2, b);
    }
}

__global__ __launch_bounds__(256) void mmd_kernel(float* out) {
    const int i = blockIdx.x;
    const int tid = threadIdx.x;

    // full-matrix sums = 2 * upper sums (diag = 0)
    const float sum1 = 2.0f * g_sumL1;
    const float sum2 = 2.0f * g_sumL2;
    const float denom = (float)(NROWS * NROWS - NROWS);  // 261632
    float bw1 = sum1 / denom * 0.01f;   // / KERNEL_MUL^(KERNEL_NUM//2)
    float bw2 = sum2 / denom * 0.01f;

    float inv1[5], inv2[5];
    inv1[0] = 1.0f / bw1;
    inv2[0] = 1.0f / bw2;
#pragma unroll
    for (int m = 1; m < 5; ++m) {
        inv1[m] = inv1[m - 1] * 0.1f;
        inv2[m] = inv2[m - 1] * 0.1f;
    }

    const bool si = (i < BHALF);
    float acc = 0.0f;
    for (int j = i + 1 + tid; j < NROWS; j += 256) {
        const int idx = i * NROWS + j;
        float l1 = g_slabL1[0][idx] + g_slabL1[1][idx] +
                   g_slabL1[2][idx] + g_slabL1[3][idx];
        float l2 = g_slabL2[0][idx] + g_slabL2[1][idx] +
                   g_slabL2[2][idx] + g_slabL2[3][idx];
        float kk = 0.0f;
#pragma unroll
        for (int m = 0; m < 5; ++m) {
            kk += __expf(-l2 * inv2[m]);
            kk += __expf(-l1 * inv1[m]);
        }
        acc += (((j < BHALF)) == si) ? kk : -kk;
    }

#pragma unroll
    for (int o = 16; o > 0; o >>= 1)
        acc += __shfl_down_sync(0xffffffffu, acc, o);
    __shared__ float rs[8];
    if ((tid & 31) == 0) rs[tid >> 5] = acc;
    __syncthreads();
    if (tid == 0) {
        float a = 0.0f;
#pragma unroll
        for (int w = 0; w < 8; ++w) a += rs[w];
        // off-diagonal pairs counted once -> x2; divide by B^2
        atomicAdd(out, a * (2.0f / 65536.0f));
    }
}

extern "C" void kernel_launch(void* const* d_in, const int* in_sizes, int n_in,
                              void* d_out, int out_size) {
    const float* src = (const float*)d_in[0];
    const float* tgt = (const float*)d_in[1];
    float* out = (float*)d_out;

    init_kernel<<<1, 1>>>(out);
    dim3 grid(36, NSPLIT);
    dist_kernel<<<grid, 256>>>(src, tgt);
    mmd_kernel<<<NROWS, 256>>>(out);
}

// round 2
// speedup vs baseline: 1.1141x; 1.1141x over previous
#include <cuda_runtime.h>

// MKMMD loss, fused persistent kernel.
// total = concat(src,tgt): N=512 rows, D=512.
// result = (10*N + 2*sum_{i<j} s_i s_j (kL2+kL1)) / B^2, s=+/-1 by half.
// bw_x = 2*S_upper_x/(N^2-N)/100 ; k = sum_{m=0..4} exp(-d/(bw*10^m))
//
// 16x16 grid of 32x32 pair tiles, upper triangle incl diag = 136 CTAs (one
// wave on 148 SMs -> spin barrier is safe). Each CTA computes full-D L1/L2
// for its 1024 pairs with packed f32x2 math, keeps them in registers across
// a device-wide barrier, then applies the 10 exponentials locally.

#define DDIM  512
#define NTIL  16
#define GRID  136
#define CH    64
#define SW    66   // odd-ish pad: conflict-free LDS.64 in compute loop

typedef unsigned long long u64;

__device__ float g_p1[GRID];
__device__ float g_p2[GRID];
__device__ float g_p3[GRID];
__device__ int   g_bar1;
__device__ int   g_bar2;

__device__ __forceinline__ u64 add2(u64 a, u64 b) {
    u64 r; asm("add.rn.f32x2 %0,%1,%2;" : "=l"(r) : "l"(a), "l"(b)); return r;
}
__device__ __forceinline__ u64 fma2(u64 a, u64 b, u64 c) {
    u64 r; asm("fma.rn.f32x2 %0,%1,%2,%3;" : "=l"(r) : "l"(a), "l"(b), "l"(c)); return r;
}
__device__ __forceinline__ float lo2(u64 a) { return __uint_as_float((unsigned)(a & 0xffffffffu)); }
__device__ __forceinline__ float hi2(u64 a) { return __uint_as_float((unsigned)(a >> 32)); }

// block reduce; valid result on thread 0 only
__device__ __forceinline__ float bred(float v, float* sbuf) {
    const int tid = threadIdx.x;
#pragma unroll
    for (int o = 16; o; o >>= 1) v += __shfl_down_sync(0xffffffffu, v, o);
    __syncthreads();                     // protect sbuf reuse across calls
    if ((tid & 31) == 0) sbuf[tid >> 5] = v;
    __syncthreads();
    float r = 0.0f;
    if (tid == 0) {
#pragma unroll
        for (int w = 0; w < 8; ++w) r += sbuf[w];
    }
    return r;
}

__global__ __launch_bounds__(256, 1) void mkmmd_kernel(
    const float* __restrict__ src, const float* __restrict__ tgt,
    float* __restrict__ out)
{
    __shared__ __align__(16) float As[32][SW];
    __shared__ __align__(16) float Bs[32][SW];   // holds NEGATED B rows
    __shared__ float sbuf[8];
    __shared__ float siv[10];                    // [0..4]=1/bwL1 ladder, [5..9]=1/bwL2

    const int tid = threadIdx.x;
    const int tx = tid & 15;
    const int ty = tid >> 4;

    // decode upper-triangle tile (ti <= tj) from blockIdx.x over 16x16 grid
    int t = blockIdx.x, ti = 0;
    while (t >= NTIL - ti) { t -= NTIL - ti; ti++; }
    const int tj = ti + t;
    const int i0 = ti * 32, j0 = tj * 32;
    const float* Ap = (i0 < 256) ? src + (size_t)i0 * DDIM : tgt + (size_t)(i0 - 256) * DDIM;
    const float* Bp = (j0 < 256) ? src + (size_t)j0 * DDIM : tgt + (size_t)(j0 - 256) * DDIM;

    // load assignment: thread handles rows lr, lr+16; 4 floats at col lc
    const int lr = tid >> 4;
    const int lc = (tid & 15) * 4;

    float4 pa0, pa1, pb0, pb1;
    pa0 = *(const float4*)(Ap + lr * DDIM + lc);
    pa1 = *(const float4*)(Ap + (lr + 16) * DDIM + lc);
    pb0 = *(const float4*)(Bp + lr * DDIM + lc);
    pb1 = *(const float4*)(Bp + (lr + 16) * DDIM + lc);

    u64 l1a[2][2] = {{0ull, 0ull}, {0ull, 0ull}};
    u64 l2a[2][2] = {{0ull, 0ull}, {0ull, 0ull}};

    for (int c = 0; c < DDIM / CH; ++c) {
        // store prefetched chunk (B negated); STS.64 keeps 8B alignment w/ SW=66
        *(float2*)&As[lr][lc]          = make_float2(pa0.x, pa0.y);
        *(float2*)&As[lr][lc + 2]      = make_float2(pa0.z, pa0.w);
        *(float2*)&As[lr + 16][lc]     = make_float2(pa1.x, pa1.y);
        *(float2*)&As[lr + 16][lc + 2] = make_float2(pa1.z, pa1.w);
        *(float2*)&Bs[lr][lc]          = make_float2(-pb0.x, -pb0.y);
        *(float2*)&Bs[lr][lc + 2]      = make_float2(-pb0.z, -pb0.w);
        *(float2*)&Bs[lr + 16][lc]     = make_float2(-pb1.x, -pb1.y);
        *(float2*)&Bs[lr + 16][lc + 2] = make_float2(-pb1.z, -pb1.w);
        __syncthreads();

        if (c < DDIM / CH - 1) {
            const int kb = (c + 1) * CH;
            pa0 = *(const float4*)(Ap + lr * DDIM + kb + lc);
            pa1 = *(const float4*)(Ap + (lr + 16) * DDIM + kb + lc);
            pb0 = *(const float4*)(Bp + lr * DDIM + kb + lc);
            pb1 = *(const float4*)(Bp + (lr + 16) * DDIM + kb + lc);
        }

#pragma unroll
        for (int k = 0; k < CH; k += 2) {
            u64 av[2], bv[2];
            av[0] = *(const u64*)&As[ty][k];
            av[1] = *(const u64*)&As[ty + 16][k];
            bv[0] = *(const u64*)&Bs[tx][k];
            bv[1] = *(const u64*)&Bs[tx + 16][k];
#pragma unroll
            for (int u = 0; u < 2; ++u)
#pragma unroll
                for (int v = 0; v < 2; ++v) {
                    u64 d  = add2(av[u], bv[v]);          // a - b (b pre-negated)
                    u64 ad = d & 0x7fffffff7fffffffULL;   // packed |d| on alu pipe
                    l2a[u][v] = fma2(d, d, l2a[u][v]);
                    l1a[u][v] = add2(l1a[u][v], ad);
                }
        }
        __syncthreads();
    }

    // collapse packed halves; masked upper-triangle partial sums for bandwidth
    float l1v[2][2], l2v[2][2];
    bool  keep[2][2];
    float s1 = 0.0f, s2 = 0.0f;
#pragma unroll
    for (int u = 0; u < 2; ++u)
#pragma unroll
        for (int v = 0; v < 2; ++v) {
            l1v[u][v] = lo2(l1a[u][v]) + hi2(l1a[u][v]);
            l2v[u][v] = lo2(l2a[u][v]) + hi2(l2a[u][v]);
            const int i = i0 + ty + 16 * u;
            const int j = j0 + tx + 16 * v;
            keep[u][v] = (ti < tj) || (j > i);
            if (keep[u][v]) { s1 += l1v[u][v]; s2 += l2v[u][v]; }
        }

    {
        float r1 = bred(s1, sbuf);
        float r2 = bred(s2, sbuf);
        if (tid == 0) {
            g_p1[blockIdx.x] = r1;
            g_p2[blockIdx.x] = r2;
            __threadfence();
            atomicAdd(&g_bar1, 1);
            while (*(volatile int*)&g_bar1 < GRID) {}
            __threadfence();
        }
        __syncthreads();   // release whole CTA once all partials visible
    }

    // bandwidth ladder: reduce the 136 partials (fixed order -> deterministic)
    {
        float v1 = 0.0f, v2 = 0.0f;
        if (tid < GRID) {
            v1 = ((volatile float*)g_p1)[tid];
            v2 = ((volatile float*)g_p2)[tid];
        }
        float S1 = bred(v1, sbuf);
        float S2 = bred(v2, sbuf);
        if (tid == 0) {
            const float c = 2.0f * 0.01f / 261632.0f;   // 2/(N^2-N)/100
            float iv1 = 1.0f / (S1 * c);
            float iv2 = 1.0f / (S2 * c);
#pragma unroll
            for (int m = 0; m < 5; ++m) {
                siv[m]     = iv1;
                siv[5 + m] = iv2;
                iv1 *= 0.1f;
                iv2 *= 0.1f;
            }
        }
        __syncthreads();
    }

    // apply 5+5 exponentials per pair (distances still in registers)
    float acc = 0.0f;
#pragma unroll
    for (int u = 0; u < 2; ++u)
#pragma unroll
        for (int v = 0; v < 2; ++v) {
            if (keep[u][v]) {
                float kv = 0.0f;
#pragma unroll
                for (int m = 0; m < 5; ++m) {
                    kv += __expf(-l1v[u][v] * siv[m]);
                    kv += __expf(-l2v[u][v] * siv[5 + m]);
                }
                acc += kv;
            }
        }

    float atot = bred(acc, sbuf);
    if (tid == 0) {
        const float sgn = ((ti < 8) == (tj < 8)) ? 1.0f : -1.0f;
        g_p3[blockIdx.x] = sgn * atot;
        __threadfence();
        int r = atomicAdd(&g_bar2, 1);
        if (r == GRID - 1) {
            __threadfence();
            float s = 0.0f;
            for (int q = 0; q < GRID; ++q) s += ((volatile float*)g_p3)[q];
            // diagonal: 512*(5+5)/B^2 ; off-diag upper pairs counted once -> x2
            out[0] = 5120.0f / 65536.0f + s * (2.0f / 65536.0f);
            g_bar1 = 0;      // reset for next graph replay (all CTAs past bar1)
            g_bar2 = 0;
            __threadfence();
        }
    }
}

extern "C" void kernel_launch(void* const* d_in, const int* in_sizes, int n_in,
                              void* d_out, int out_size) {
    const float* src = (const float*)d_in[0];
    const float* tgt = (const float*)d_in[1];
    float* out = (float*)d_out;
    mkmmd_kernel<<<GRID, 256>>>(src, tgt, out);
}

// round 3
// speedup vs baseline: 1.2058x; 1.0823x over previous
#include <cuda_runtime.h>

// MKMMD loss, fused persistent kernel (R3: LDS.128 + double-buffer + imm offsets).
// total = concat(src,tgt): N=512 rows, D=512.
// result = (10*N + 2*sum_{i<j} s_i s_j (kL2+kL1)) / B^2, s=+/-1 by half.
// bw_x = 2*S_upper_x/(N^2-N)/100 ; k = sum_{m=0..4} exp(-d/(bw*10^m))

#define DDIM  512
#define NTIL  16
#define GRID  136
#define CH    64
#define SW    68   // 272B row stride: 16B-aligned for LDS.128

typedef unsigned long long u64;

__device__ float g_p1[GRID];
__device__ float g_p2[GRID];
__device__ float g_p3[GRID];
__device__ int   g_bar1;
__device__ int   g_bar2;

__device__ __forceinline__ u64 add2(u64 a, u64 b) {
    u64 r; asm("add.rn.f32x2 %0,%1,%2;" : "=l"(r) : "l"(a), "l"(b)); return r;
}
__device__ __forceinline__ u64 fma2(u64 a, u64 b, u64 c) {
    u64 r; asm("fma.rn.f32x2 %0,%1,%2,%3;" : "=l"(r) : "l"(a), "l"(b), "l"(c)); return r;
}
__device__ __forceinline__ float lo2(u64 a) { return __uint_as_float((unsigned)(a & 0xffffffffu)); }
__device__ __forceinline__ float hi2(u64 a) { return __uint_as_float((unsigned)(a >> 32)); }

// block reduce; valid result on thread 0 only
__device__ __forceinline__ float bred(float v, float* sbuf) {
    const int tid = threadIdx.x;
#pragma unroll
    for (int o = 16; o; o >>= 1) v += __shfl_down_sync(0xffffffffu, v, o);
    __syncthreads();
    if ((tid & 31) == 0) sbuf[tid >> 5] = v;
    __syncthreads();
    float r = 0.0f;
    if (tid == 0) {
#pragma unroll
        for (int w = 0; w < 8; ++w) r += sbuf[w];
    }
    return r;
}

// one chunk (64 k-values) of packed L1/L2 accumulation
__device__ __forceinline__ void compute_chunk(
    const float* __restrict__ As, const float* __restrict__ Bs,
    int ty, int tx, u64 l1a[2][2], u64 l2a[2][2])
{
    const ulonglong2* __restrict__ a0 = (const ulonglong2*)(As + ty * SW);
    const ulonglong2* __restrict__ a1 = (const ulonglong2*)(As + (ty + 16) * SW);
    const ulonglong2* __restrict__ b0 = (const ulonglong2*)(Bs + tx * SW);
    const ulonglong2* __restrict__ b1 = (const ulonglong2*)(Bs + (tx + 16) * SW);

#pragma unroll
    for (int q = 0; q < CH / 4; ++q) {          // 4 k per q, imm-offset LDS.128
        ulonglong2 A0 = a0[q], A1 = a1[q], B0 = b0[q], B1 = b1[q];
#pragma unroll
        for (int h = 0; h < 2; ++h) {           // low / high packed pair
            u64 av[2], bv[2];
            av[0] = h ? A0.y : A0.x;
            av[1] = h ? A1.y : A1.x;
            bv[0] = h ? B0.y : B0.x;
            bv[1] = h ? B1.y : B1.x;
#pragma unroll
            for (int u = 0; u < 2; ++u)
#pragma unroll
                for (int v = 0; v < 2; ++v) {
                    u64 d  = add2(av[u], bv[v]);          // a - b (b pre-negated)
                    u64 ad = d & 0x7fffffff7fffffffULL;   // packed |d| (alu pipe)
                    l2a[u][v] = fma2(d, d, l2a[u][v]);
                    l1a[u][v] = add2(l1a[u][v], ad);
                }
        }
    }
}

__global__ __launch_bounds__(256, 1) void mkmmd_kernel(
    const float* __restrict__ src, const float* __restrict__ tgt,
    float* __restrict__ out)
{
    __shared__ __align__(16) float As[2][32][SW];
    __shared__ __align__(16) float Bs[2][32][SW];   // holds NEGATED B rows
    __shared__ float sbuf[8];
    __shared__ float siv[10];

    const int tid = threadIdx.x;
    const int tx = tid & 15;
    const int ty = tid >> 4;

    // decode upper-triangle tile (ti <= tj) over 16x16 grid
    int t = blockIdx.x, ti = 0;
    while (t >= NTIL - ti) { t -= NTIL - ti; ti++; }
    const int tj = ti + t;
    const int i0 = ti * 32, j0 = tj * 32;
    const float* Ap = (i0 < 256) ? src + (size_t)i0 * DDIM : tgt + (size_t)(i0 - 256) * DDIM;
    const float* Bp = (j0 < 256) ? src + (size_t)j0 * DDIM : tgt + (size_t)(j0 - 256) * DDIM;

    // load assignment: rows lr, lr+16; float4 at col lc
    const int lr = tid >> 4;
    const int lc = (tid & 15) * 4;

    u64 l1a[2][2] = {{0ull, 0ull}, {0ull, 0ull}};
    u64 l2a[2][2] = {{0ull, 0ull}, {0ull, 0ull}};

    float4 pa0 = *(const float4*)(Ap + lr * DDIM + lc);
    float4 pa1 = *(const float4*)(Ap + (lr + 16) * DDIM + lc);
    float4 pb0 = *(const float4*)(Bp + lr * DDIM + lc);
    float4 pb1 = *(const float4*)(Bp + (lr + 16) * DDIM + lc);

    for (int c = 0; c < DDIM / CH; ++c) {
        const int p = c & 1;
        // store prefetched chunk (B negated); STS.128, 16B aligned
        *(float4*)&As[p][lr][lc]      = pa0;
        *(float4*)&As[p][lr + 16][lc] = pa1;
        *(float4*)&Bs[p][lr][lc]      = make_float4(-pb0.x, -pb0.y, -pb0.z, -pb0.w);
        *(float4*)&Bs[p][lr + 16][lc] = make_float4(-pb1.x, -pb1.y, -pb1.z, -pb1.w);
        __syncthreads();

        if (c < DDIM / CH - 1) {
            const int kb = (c + 1) * CH;
            pa0 = *(const float4*)(Ap + lr * DDIM + kb + lc);
            pa1 = *(const float4*)(Ap + (lr + 16) * DDIM + kb + lc);
            pb0 = *(const float4*)(Bp + lr * DDIM + kb + lc);
            pb1 = *(const float4*)(Bp + (lr + 16) * DDIM + kb + lc);
        }

        compute_chunk(&As[p][0][0], &Bs[p][0][0], ty, tx, l1a, l2a);
        // single sync per chunk: everyone past this sync has finished
        // compute(c-1), so next iteration's STS into buffer 1-p is safe.
    }

    // collapse packed halves; masked upper-triangle partial sums for bandwidth
    float l1v[2][2], l2v[2][2];
    bool  keep[2][2];
    float s1 = 0.0f, s2 = 0.0f;
#pragma unroll
    for (int u = 0; u < 2; ++u)
#pragma unroll
        for (int v = 0; v < 2; ++v) {
            l1v[u][v] = lo2(l1a[u][v]) + hi2(l1a[u][v]);
            l2v[u][v] = lo2(l2a[u][v]) + hi2(l2a[u][v]);
            const int i = i0 + ty + 16 * u;
            const int j = j0 + tx + 16 * v;
            keep[u][v] = (ti < tj) || (j > i);
            if (keep[u][v]) { s1 += l1v[u][v]; s2 += l2v[u][v]; }
        }

    {
        float r1 = bred(s1, sbuf);
        float r2 = bred(s2, sbuf);
        if (tid == 0) {
            g_p1[blockIdx.x] = r1;
            g_p2[blockIdx.x] = r2;
            __threadfence();
            atomicAdd(&g_bar1, 1);
            while (*(volatile int*)&g_bar1 < GRID) {}
            __threadfence();
        }
        __syncthreads();
    }

    // bandwidth ladder from the 136 partials (fixed order -> deterministic)
    {
        float v1 = 0.0f, v2 = 0.0f;
        if (tid < GRID) {
            v1 = ((volatile float*)g_p1)[tid];
            v2 = ((volatile float*)g_p2)[tid];
        }
        float S1 = bred(v1, sbuf);
        float S2 = bred(v2, sbuf);
        if (tid == 0) {
            const float cc = 2.0f * 0.01f / 261632.0f;   // 2/(N^2-N)/100
            float iv1 = 1.0f / (S1 * cc);
            float iv2 = 1.0f / (S2 * cc);
#pragma unroll
            for (int m = 0; m < 5; ++m) {
                siv[m]     = iv1;
                siv[5 + m] = iv2;
                iv1 *= 0.1f;
                iv2 *= 0.1f;
            }
        }
        __syncthreads();
    }

    // 5+5 exponentials per pair (distances still in registers)
    float acc = 0.0f;
#pragma unroll
    for (int u = 0; u < 2; ++u)
#pragma unroll
        for (int v = 0; v < 2; ++v) {
            if (keep[u][v]) {
                float kv = 0.0f;
#pragma unroll
                for (int m = 0; m < 5; ++m) {
                    kv += __expf(-l1v[u][v] * siv[m]);
                    kv += __expf(-l2v[u][v] * siv[5 + m]);
                }
                acc += kv;
            }
        }

    float atot = bred(acc, sbuf);
    if (tid == 0) {
        const float sgn = ((ti < 8) == (tj < 8)) ? 1.0f : -1.0f;
        g_p3[blockIdx.x] = sgn * atot;
        __threadfence();
        int r = atomicAdd(&g_bar2, 1);
        if (r == GRID - 1) {
            __threadfence();
            float s = 0.0f;
            for (int q = 0; q < GRID; ++q) s += ((volatile float*)g_p3)[q];
            out[0] = 5120.0f / 65536.0f + s * (2.0f / 65536.0f);
            g_bar1 = 0;      // reset for next graph replay
            g_bar2 = 0;
            __threadfence();
        }
    }
}

extern "C" void kernel_launch(void* const* d_in, const int* in_sizes, int n_in,
                              void* d_out, int out_size) {
    const float* src = (const float*)d_in[0];
    const float* tgt = (const float*)d_in[1];
    float* out = (float*)d_out;
    mkmmd_kernel<<<GRID, 256>>>(src, tgt, out);
}